// round 12
// baseline (speedup 1.0000x reference)
#include <cuda_runtime.h>
#include <cuda_fp16.h>
#include <mma.h>
#include <math.h>
#include <stdint.h>

using namespace nvcuda;

#define N_NODES 100000
#define N_EDGES 1600000
#define HID 64
#define NH (N_NODES * HID)
#define NEG 0.2f
#define SCAN_BLOCKS 98   // ceil(100000/1024)

#define TILE_M 128
#define N_TILES 782      // ceil(100000/128)

// LSTM tensor-kernel smem layout
#define LDA 136                          // halves per A row (pad 8)
#define LDG 260                          // floats per gate row (pad 4)
#define SM_A_BYTES (128 * LDA * 2)       // 34816
#define SM_G_BYTES (128 * LDG * 4)       // 133120
#define SM_TOTAL (SM_A_BYTES + SM_G_BYTES)

// ---------------- scratch (static device globals; no runtime alloc) ----------
__device__ __align__(16) __half g_xsh[NH];  // projected features fp16 [N,64]
__device__ __align__(16) float g_xb[NH];    // GAT output (tanh)  [N,64]
__device__ float g_asrc[N_NODES];
__device__ float g_adst[N_NODES];
__device__ int   g_cnt[N_NODES];
__device__ int   g_rowptr[N_NODES + 1];
__device__ int   g_cursor[N_NODES];
__device__ int   g_bsum[SCAN_BLOCKS];
__device__ int   g_boff[SCAN_BLOCKS];
__device__ int   g_csr[N_EDGES];    // src node per CSR slot (grouped by dst)
__device__ int   g_is64;            // 1 if edge_index marshaled as int64, else int32
// fp16 B = [Wih | Whh] row-major [256 gates][128 k]  (64KB, L1/L2 resident)
__device__ __align__(16) __half g_Bh16[256 * 128];

// ---------------- packed f32x2 helpers ---------------------------------------
__device__ __forceinline__ unsigned long long pk2(float lo, float hi) {
    unsigned long long r;
    asm("mov.b64 %0, {%1, %2};" : "=l"(r) : "f"(lo), "f"(hi));
    return r;
}
__device__ __forceinline__ unsigned long long fma2(unsigned long long a,
                                                   unsigned long long b,
                                                   unsigned long long c) {
    unsigned long long d;
    asm("fma.rn.f32x2 %0, %1, %2, %3;" : "=l"(d) : "l"(a), "l"(b), "l"(c));
    return d;
}
__device__ __forceinline__ unsigned long long add2(unsigned long long a,
                                                   unsigned long long b) {
    unsigned long long d;
    asm("add.rn.f32x2 %0, %1, %2;" : "=l"(d) : "l"(a), "l"(b));
    return d;
}
__device__ __forceinline__ float2 up2(unsigned long long v) {
    float2 f;
    asm("mov.b64 {%0, %1}, %2;" : "=f"(f.x), "=f"(f.y) : "l"(v));
    return f;
}

// ---------------- fused: dtype probe (block 0) + cnt zero (blocks 1..392) ----
__global__ void k_detect(const int* __restrict__ eiw) {
    if (blockIdx.x == 0) {
        __shared__ int s_any;
        if (threadIdx.x == 0) s_any = 0;
        __syncthreads();
        if (eiw[2 * threadIdx.x + 1] != 0) s_any = 1;   // benign race
        __syncthreads();
        if (threadIdx.x == 0) g_is64 = (s_any == 0);
        return;
    }
    int i = (blockIdx.x - 1) * 256 + threadIdx.x;
    if (i < N_NODES) g_cnt[i] = 0;
}
__device__ __forceinline__ int edge_at(const int* __restrict__ eiw, int idx) {
    return g_is64 ? eiw[2 * idx] : eiw[idx];
}

// ---------------- kernel 1: xs = x @ W (fp16 out),  a_src, a_dst -------------
__global__ void k_proj(const float* __restrict__ x, const float* __restrict__ W,
                       const float* __restrict__ att_s, const float* __restrict__ att_d) {
    __shared__ float Wsm[64 * 64];
    __shared__ __align__(16) float xt[8 * 64];
    __shared__ float part[4][2][4];

    const int tx = threadIdx.x;          // 0..63 (col)
    const int ty = threadIdx.y;          // 0..3
    const int tid = ty * 64 + tx;        // 0..255
    const int row0 = blockIdx.x * 8;

    for (int i = tid; i < 4096; i += 256) Wsm[i] = W[i];
    for (int i = tid; i < 512; i += 256) xt[i] = x[row0 * 64 + i];
    const float as_v = att_s[tx];
    const float ad_v = att_d[tx];
    __syncthreads();

    const float4* xr0 = (const float4*)&xt[ty * 64];
    const float4* xr1 = (const float4*)&xt[(ty + 4) * 64];
    float acc0 = 0.f, acc1 = 0.f;
    #pragma unroll
    for (int kk = 0; kk < 16; kk++) {
        float4 a = xr0[kk];
        float4 b = xr1[kk];
        float w0 = Wsm[(4 * kk + 0) * 64 + tx];
        float w1 = Wsm[(4 * kk + 1) * 64 + tx];
        float w2 = Wsm[(4 * kk + 2) * 64 + tx];
        float w3 = Wsm[(4 * kk + 3) * 64 + tx];
        acc0 += a.x * w0 + a.y * w1 + a.z * w2 + a.w * w3;
        acc1 += b.x * w0 + b.y * w1 + b.z * w2 + b.w * w3;
    }
    g_xsh[(row0 + ty) * 64 + tx]     = __float2half_rn(acc0);
    g_xsh[(row0 + ty + 4) * 64 + tx] = __float2half_rn(acc1);

    float p0 = acc0 * as_v;
    float p1 = acc1 * as_v;
    float p2 = acc0 * ad_v;
    float p3 = acc1 * ad_v;
    #pragma unroll
    for (int o = 16; o; o >>= 1) {
        p0 += __shfl_xor_sync(0xffffffffu, p0, o);
        p1 += __shfl_xor_sync(0xffffffffu, p1, o);
        p2 += __shfl_xor_sync(0xffffffffu, p2, o);
        p3 += __shfl_xor_sync(0xffffffffu, p3, o);
    }
    if ((tx & 31) == 0) {
        int hh = tx >> 5;
        part[ty][hh][0] = p0; part[ty][hh][1] = p1;
        part[ty][hh][2] = p2; part[ty][hh][3] = p3;
    }
    __syncthreads();
    if (tid < 16) {
        int t = tid & 3, w = tid >> 2;
        float v = part[t][0][w] + part[t][1][w];
        if (w == 0)      g_asrc[row0 + t]     = v;
        else if (w == 1) g_asrc[row0 + t + 4] = v;
        else if (w == 2) g_adst[row0 + t]     = v;
        else             g_adst[row0 + t + 4] = v;
    }
}

// ---------------- CSR build --------------------------------------------------
__global__ void k_count(const int* __restrict__ eiw) {
    int e = blockIdx.x * blockDim.x + threadIdx.x;
    if (e < N_EDGES) {
        int dst = edge_at(eiw, N_EDGES + e);
        if ((unsigned)dst < (unsigned)N_NODES) atomicAdd(&g_cnt[dst], 1);
    }
}
__global__ void k_scan1() {
    __shared__ int sm[1024];
    int i = blockIdx.x * 1024 + threadIdx.x;
    int v = (i < N_NODES) ? g_cnt[i] : 0;
    sm[threadIdx.x] = v;
    __syncthreads();
    for (int off = 1; off < 1024; off <<= 1) {
        int t = 0;
        if ((int)threadIdx.x >= off) t = sm[threadIdx.x - off];
        __syncthreads();
        sm[threadIdx.x] += t;
        __syncthreads();
    }
    if (i < N_NODES) g_rowptr[i] = sm[threadIdx.x] - v;
    if (threadIdx.x == 1023) g_bsum[blockIdx.x] = sm[1023];
}
__global__ void k_scan2() {   // 128-thread smem scan over SCAN_BLOCKS sums
    __shared__ int sm[128];
    int t = threadIdx.x;
    int v = (t < SCAN_BLOCKS) ? g_bsum[t] : 0;
    sm[t] = v;
    __syncthreads();
    #pragma unroll
    for (int off = 1; off < 128; off <<= 1) {
        int u = (t >= off) ? sm[t - off] : 0;
        __syncthreads();
        sm[t] += u;
        __syncthreads();
    }
    if (t < SCAN_BLOCKS) g_boff[t] = sm[t] - v;   // exclusive
}
__global__ void k_scan3() {
    int i = blockIdx.x * 1024 + threadIdx.x;
    if (i < N_NODES) {
        int v = g_rowptr[i] + g_boff[blockIdx.x];
        g_rowptr[i] = v;
        g_cursor[i] = v;
    }
    if (i == 0) g_rowptr[N_NODES] = N_EDGES;
}
__global__ void k_fill(const int* __restrict__ eiw) {
    int e = blockIdx.x * blockDim.x + threadIdx.x;
    if (e < N_EDGES) {
        int dst = edge_at(eiw, N_EDGES + e);
        int src = edge_at(eiw, e);
        if ((unsigned)dst < (unsigned)N_NODES && (unsigned)src < (unsigned)N_NODES) {
            int pos = atomicAdd(&g_cursor[dst], 1);
            if ((unsigned)pos < (unsigned)N_EDGES) g_csr[pos] = src;
        }
    }
}

// ---------------- kernel: build fp16 B = [Wih | Whh], row-major [256][128] ---
__global__ void k_prep(const float* __restrict__ Wih, const float* __restrict__ Whh) {
    int idx = blockIdx.x * 256 + threadIdx.x;   // 0..32767
    int g = idx >> 7;
    int k = idx & 127;
    float v = (k < 64) ? Wih[g * 64 + k] : Whh[g * 64 + (k - 64)];
    g_Bh16[idx] = __float2half_rn(v);
}

// ---------------- kernel 3: paired-half fp16-gather softmax aggregation ------
// One warp per node. Two 16-lane halves process 2 edges/iteration; each lane
// gathers 4 feature dims as fp16 (LDG.64), converts, accumulates fp32 FFMA2.
__global__ void k_agg(const float* __restrict__ bias) {
    const int warp = threadIdx.x >> 5;
    const int lane = threadIdx.x & 31;
    const int node = blockIdx.x * 8 + warp;

    const int start = g_rowptr[node];
    const int deg   = g_rowptr[node + 1] - start;
    const float adst = g_adst[node];

    const int hf = lane >> 4;        // which edge of the pair
    const int dl = lane & 15;        // dim group: dims 4*dl .. 4*dl+3

    unsigned long long accA = 0ull;  // dims (4dl, 4dl+1)
    unsigned long long accB = 0ull;  // dims (4dl+2, 4dl+3)
    float z = 0.f;

    for (int base = 0; base < deg; base += 32) {
        int k = base + lane;
        float p = 0.f;
        int s = 0;
        if (k < deg) {
            s = g_csr[start + k];
            float e = g_asrc[s] + adst;
            e = fmaxf(e, NEG * e);
            p = __expf(e);
        }
        z += p;
        int cnt = min(32, deg - base);
        int npair = (cnt + 1) >> 1;
        #pragma unroll 2
        for (int t = 0; t < npair; t++) {
            int srcl = 2 * t + hf;           // lane cnt (if hit) holds p=0 pad
            float pj = __shfl_sync(0xffffffffu, p, srcl);
            int   sj = __shfl_sync(0xffffffffu, s, srcl);
            uint2 v = *(const uint2*)&g_xsh[sj * HID + 4 * dl];
            float2 f0 = __half22float2(*(__half2*)&v.x);
            float2 f1 = __half22float2(*(__half2*)&v.y);
            unsigned long long pp = pk2(pj, pj);
            accA = fma2(pk2(f0.x, f0.y), pp, accA);
            accB = fma2(pk2(f1.x, f1.y), pp, accB);
        }
    }
    // combine the two halves
    accA = add2(accA, __shfl_xor_sync(0xffffffffu, accA, 16));
    accB = add2(accB, __shfl_xor_sync(0xffffffffu, accB, 16));
    // z reduce over all 32 lanes
    #pragma unroll
    for (int o = 16; o; o >>= 1) z += __shfl_xor_sync(0xffffffffu, z, o);

    if (hf == 0) {
        float inv = 1.f / (z + 1e-16f);
        float2 a = up2(accA);
        float2 b = up2(accB);
        float4 bv = *(const float4*)&bias[4 * dl];
        float4 r;
        r.x = tanhf(a.x * inv + bv.x);
        r.y = tanhf(a.y * inv + bv.y);
        r.z = tanhf(b.x * inv + bv.z);
        r.w = tanhf(b.y * inv + bv.w);
        *(float4*)&g_xb[node * HID + 4 * dl] = r;
    }
}

// ---------------- kernel 4: WMMA fp16 LSTM step ------------------------------
__device__ __forceinline__ float sigf(float v) { return 1.f / (1.f + __expf(-v)); }

__global__ void __launch_bounds__(512, 1) k_lstm_wmma(
        const float* __restrict__ h_in, const float* __restrict__ c_in,
        float* __restrict__ out) {
    extern __shared__ unsigned char sm_raw[];
    __half* Asm = (__half*)sm_raw;                       // [128][LDA]
    float*  Gsm = (float*)(sm_raw + SM_A_BYTES);         // [128][LDG]

    const int tid = threadIdx.x;
    const int wid = tid >> 5;
    const int row0 = blockIdx.x * TILE_M;

    // stage A: fp32 -> fp16 (xb cols 0..63, h cols 64..127)
    for (int idx = tid; idx < 8192; idx += 512) {
        int row = idx >> 6;
        int k = (idx & 63) * 2;
        int grow = row0 + row;
        float2 f = make_float2(0.f, 0.f);
        if (grow < N_NODES) {
            f = (k < 64) ? *(const float2*)&g_xb[grow * 64 + k]
                         : *(const float2*)&h_in[grow * 64 + (k - 64)];
        }
        *(__half2*)&Asm[row * LDA + k] = __floats2half2_rn(f.x, f.y);
    }
    __syncthreads();

    // MMA: each warp 32 rows x 64 gates
    {
        const int wm = wid & 3;
        const int wn = wid >> 2;
        wmma::fragment<wmma::accumulator, 16, 16, 16, float> acc[2][4];
        #pragma unroll
        for (int i = 0; i < 2; i++)
            #pragma unroll
            for (int j = 0; j < 4; j++)
                wmma::fill_fragment(acc[i][j], 0.f);

        #pragma unroll
        for (int kk = 0; kk < 8; kk++) {
            wmma::fragment<wmma::matrix_a, 16, 16, 16, __half, wmma::row_major> a[2];
            #pragma unroll
            for (int i = 0; i < 2; i++)
                wmma::load_matrix_sync(a[i], Asm + (wm * 32 + i * 16) * LDA + kk * 16, LDA);
            #pragma unroll
            for (int j = 0; j < 4; j++) {
                wmma::fragment<wmma::matrix_b, 16, 16, 16, __half, wmma::col_major> b;
                wmma::load_matrix_sync(b, g_Bh16 + (wn * 64 + j * 16) * 128 + kk * 16, 128);
                wmma::mma_sync(acc[0][j], a[0], b, acc[0][j]);
                wmma::mma_sync(acc[1][j], a[1], b, acc[1][j]);
            }
        }
        #pragma unroll
        for (int i = 0; i < 2; i++)
            #pragma unroll
            for (int j = 0; j < 4; j++)
                wmma::store_matrix_sync(Gsm + (wm * 32 + i * 16) * LDG + wn * 64 + j * 16,
                                        acc[i][j], LDG, wmma::mem_row_major);
    }
    __syncthreads();

    // epilogue: torch gate order i,f,g,o
    const int row = tid >> 2;
    const int q = tid & 3;
    const int grow = row0 + row;
    if (grow < N_NODES) {
        const float* grow_g = Gsm + row * LDG;
        #pragma unroll
        for (int v4 = 0; v4 < 4; v4++) {
            int d = q * 16 + v4 * 4;
            float4 c0 = *(const float4*)&c_in[grow * 64 + d];
            float4 hv, cv;
            #pragma unroll
            for (int t = 0; t < 4; t++) {
                float ig = grow_g[d + t];
                float fg = grow_g[64 + d + t];
                float gv = grow_g[128 + d + t];
                float og = grow_g[192 + d + t];
                float c0v = (&c0.x)[t];
                float c1 = sigf(fg) * c0v + sigf(ig) * tanhf(gv);
                float h1 = sigf(og) * tanhf(c1);
                (&hv.x)[t] = h1;
                (&cv.x)[t] = c1;
            }
            *(float4*)&out[grow * 64 + d]          = hv;   // h1 flat
            *(float4*)&out[NH + grow * 64 + d]     = hv;   // h1[None]
            *(float4*)&out[2 * NH + grow * 64 + d] = cv;   // c1[None]
        }
    }
}

// ---------------- launch: fork-join two-branch graph -------------------------
extern "C" void kernel_launch(void* const* d_in, const int* in_sizes, int n_in,
                              void* d_out, int out_size) {
    const float* x   = (const float*)d_in[0];
    const int*   eiw = (const int*)d_in[1];     // edge_index, dtype-probed on device
    const float* h   = (const float*)d_in[2];
    const float* c   = (const float*)d_in[3];
    const float* Wg  = (const float*)d_in[4];
    const float* as  = (const float*)d_in[5];
    const float* ad  = (const float*)d_in[6];
    const float* bg  = (const float*)d_in[7];
    const float* Wih = (const float*)d_in[8];
    const float* Whh = (const float*)d_in[9];
    float* out = (float*)d_out;

    // lazily created handles (first call runs outside graph capture)
    static cudaStream_t s2 = nullptr;
    static cudaEvent_t evFork = nullptr, evJoin = nullptr;
    if (s2 == nullptr) {
        cudaStreamCreateWithFlags(&s2, cudaStreamNonBlocking);
        cudaEventCreateWithFlags(&evFork, cudaEventDisableTiming);
        cudaEventCreateWithFlags(&evJoin, cudaEventDisableTiming);
    }

    cudaFuncSetAttribute(k_lstm_wmma, cudaFuncAttributeMaxDynamicSharedMemorySize, SM_TOTAL);

    // main stream: dtype probe + cnt zero, then fork
    k_detect<<<393, 256>>>(eiw);
    cudaEventRecord(evFork, 0);
    cudaStreamWaitEvent(s2, evFork, 0);

    // branch B (side stream): CSR build chain
    k_count<<<(N_EDGES + 255) / 256, 256, 0, s2>>>(eiw);
    k_scan1<<<SCAN_BLOCKS, 1024, 0, s2>>>();
    k_scan2<<<1, 128, 0, s2>>>();
    k_scan3<<<SCAN_BLOCKS, 1024, 0, s2>>>();
    k_fill<<<(N_EDGES + 255) / 256, 256, 0, s2>>>(eiw);
    cudaEventRecord(evJoin, s2);

    // branch A (main stream): projection + weight prep
    k_proj<<<N_NODES / 8, dim3(64, 4)>>>(x, Wg, as, ad);
    k_prep<<<128, 256>>>(Wih, Whh);

    // join, then aggregation + LSTM
    cudaStreamWaitEvent(0, evJoin, 0);
    k_agg<<<N_NODES / 8, 256>>>(bg);
    k_lstm_wmma<<<N_TILES, 512, SM_TOTAL>>>(h, c, out);
}

// round 13
// speedup vs baseline: 1.2506x; 1.2506x over previous
#include <cuda_runtime.h>
#include <cuda_fp16.h>
#include <mma.h>
#include <math.h>
#include <stdint.h>

using namespace nvcuda;

#define N_NODES 100000
#define N_EDGES 1600000
#define HID 64
#define NH (N_NODES * HID)
#define NEG 0.2f
#define SCAN_BLOCKS 98   // ceil(100000/1024)

#define TILE_M 128
#define N_TILES 782      // ceil(100000/128)

// LSTM tensor-kernel smem layout
#define LDA 136                          // halves per A row (pad 8)
#define LDG 260                          // floats per gate row (pad 4)
#define SM_A_BYTES (128 * LDA * 2)       // 34816
#define SM_G_BYTES (128 * LDG * 4)       // 133120
#define SM_TOTAL (SM_A_BYTES + SM_G_BYTES)

// proj tensor-kernel: A [128][72] fp16 (18432B) + W [64][72] fp16 (9216B),
// then G [128][68] fp32 (34816B) aliased over the same buffer after MMA.
#define PLDA 72
#define PLDW 72
#define PLDG 68
#define PBUF_BYTES 34816

// ---------------- scratch (static device globals; no runtime alloc) ----------
__device__ __align__(16) float g_xs[NH];    // projected features [N,64] fp32
__device__ __align__(16) float g_xb[NH];    // GAT output (tanh)  [N,64]
__device__ float g_asrc[N_NODES];
__device__ float g_adst[N_NODES];
__device__ int   g_cnt[N_NODES];
__device__ int   g_rowptr[N_NODES + 1];
__device__ int   g_cursor[N_NODES];
__device__ int   g_bsum[SCAN_BLOCKS];
__device__ int   g_boff[SCAN_BLOCKS];
__device__ int   g_csr[N_EDGES];    // src node per CSR slot (grouped by dst)
__device__ int   g_is64;            // 1 if edge_index marshaled as int64, else int32
// fp16 B = [Wih | Whh] row-major [256 gates][128 k]  (64KB, L1/L2 resident)
__device__ __align__(16) __half g_Bh16[256 * 128];
// fp16 W_gat [64 k][64 n] row-major (8KB)
__device__ __align__(16) __half g_Wgh16[64 * 64];

// ---------------- packed f32x2 helpers ---------------------------------------
__device__ __forceinline__ unsigned long long pk2(float lo, float hi) {
    unsigned long long r;
    asm("mov.b64 %0, {%1, %2};" : "=l"(r) : "f"(lo), "f"(hi));
    return r;
}
__device__ __forceinline__ unsigned long long fma2(unsigned long long a,
                                                   unsigned long long b,
                                                   unsigned long long c) {
    unsigned long long d;
    asm("fma.rn.f32x2 %0, %1, %2, %3;" : "=l"(d) : "l"(a), "l"(b), "l"(c));
    return d;
}
__device__ __forceinline__ unsigned long long add2(unsigned long long a,
                                                   unsigned long long b) {
    unsigned long long d;
    asm("add.rn.f32x2 %0, %1, %2;" : "=l"(d) : "l"(a), "l"(b));
    return d;
}
__device__ __forceinline__ float2 up2(unsigned long long v) {
    float2 f;
    asm("mov.b64 {%0, %1}, %2;" : "=f"(f.x), "=f"(f.y) : "l"(v));
    return f;
}

// ---------------- fused: dtype probe (block 0) + cnt zero (blocks 1..392) ----
__global__ void k_detect(const int* __restrict__ eiw) {
    if (blockIdx.x == 0) {
        __shared__ int s_any;
        if (threadIdx.x == 0) s_any = 0;
        __syncthreads();
        if (eiw[2 * threadIdx.x + 1] != 0) s_any = 1;   // benign race
        __syncthreads();
        if (threadIdx.x == 0) g_is64 = (s_any == 0);
        return;
    }
    int i = (blockIdx.x - 1) * 256 + threadIdx.x;
    if (i < N_NODES) g_cnt[i] = 0;
}
__device__ __forceinline__ int edge_at(const int* __restrict__ eiw, int idx) {
    return g_is64 ? eiw[2 * idx] : eiw[idx];
}

// ---------------- kernel: fp16 weight preps (B = [Wih|Whh], W_gat) -----------
__global__ void k_prep(const float* __restrict__ Wih, const float* __restrict__ Whh,
                       const float* __restrict__ Wg) {
    int idx = blockIdx.x * 256 + threadIdx.x;   // 0..32767
    int g = idx >> 7;
    int k = idx & 127;
    float v = (k < 64) ? Wih[g * 64 + k] : Whh[g * 64 + (k - 64)];
    g_Bh16[idx] = __float2half_rn(v);
    if (idx < 4096) g_Wgh16[idx] = __float2half_rn(Wg[idx]);
}

// ---------------- kernel 1: WMMA xs = x @ W (smem-staged W) ------------------
// One CTA per 128-row tile; 8 warps = 4(M) x 2(N), each warp 32 rows x 32 cols.
__global__ void __launch_bounds__(256) k_proj_wmma(
        const float* __restrict__ x,
        const float* __restrict__ att_s, const float* __restrict__ att_d) {
    __shared__ __align__(16) unsigned char buf[PBUF_BYTES];
    __shared__ float sa[64], sd[64];
    __half* Ax  = (__half*)buf;                  // [128][PLDA]
    __half* Wsm = (__half*)(buf + 128 * PLDA * 2);  // [64][PLDW] at 18432
    float*  Gx  = (float*)buf;                   // [128][PLDG], aliases after MMA

    const int tid = threadIdx.x;
    const int wid = tid >> 5;
    const int row0 = blockIdx.x * TILE_M;

    if (tid < 64) sa[tid] = att_s[tid];
    else if (tid < 128) sd[tid - 64] = att_d[tid - 64];

    // stage W fp16 [64 k][64 n] -> smem (coalesced half2)
    for (int idx = tid; idx < 2048; idx += 256) {
        int k = idx >> 5;
        int n2 = (idx & 31) * 2;
        *(__half2*)&Wsm[k * PLDW + n2] = *(const __half2*)&g_Wgh16[k * 64 + n2];
    }
    // stage x -> fp16 smem
    for (int idx = tid; idx < 4096; idx += 256) {
        int row = idx >> 5;
        int k = (idx & 31) * 2;
        int grow = row0 + row;
        float2 f = make_float2(0.f, 0.f);
        if (grow < N_NODES) f = *(const float2*)&x[grow * 64 + k];
        *(__half2*)&Ax[row * PLDA + k] = __floats2half2_rn(f.x, f.y);
    }
    __syncthreads();

    // MMA: K=64 in 4 steps, all fragments from smem
    {
        const int wm = wid & 3;       // rows wm*32 .. +31
        const int wn = wid >> 2;      // cols wn*32 .. +31
        wmma::fragment<wmma::accumulator, 16, 16, 16, float> acc[2][2];
        #pragma unroll
        for (int i = 0; i < 2; i++)
            #pragma unroll
            for (int j = 0; j < 2; j++)
                wmma::fill_fragment(acc[i][j], 0.f);

        #pragma unroll
        for (int kk = 0; kk < 4; kk++) {
            wmma::fragment<wmma::matrix_a, 16, 16, 16, __half, wmma::row_major> a[2];
            #pragma unroll
            for (int i = 0; i < 2; i++)
                wmma::load_matrix_sync(a[i], Ax + (wm * 32 + i * 16) * PLDA + kk * 16, PLDA);
            #pragma unroll
            for (int j = 0; j < 2; j++) {
                wmma::fragment<wmma::matrix_b, 16, 16, 16, __half, wmma::row_major> b;
                wmma::load_matrix_sync(b, Wsm + (kk * 16) * PLDW + wn * 32 + j * 16, PLDW);
                wmma::mma_sync(acc[0][j], a[0], b, acc[0][j]);
                wmma::mma_sync(acc[1][j], a[1], b, acc[1][j]);
            }
        }
        __syncthreads();   // all warps done reading Ax/Wsm; safe to alias with Gx
        #pragma unroll
        for (int i = 0; i < 2; i++)
            #pragma unroll
            for (int j = 0; j < 2; j++)
                wmma::store_matrix_sync(Gx + (wm * 32 + i * 16) * PLDG + wn * 32 + j * 16,
                                        acc[i][j], PLDG, wmma::mem_row_major);
    }
    __syncthreads();

    // coalesced fp32 xs store
    for (int idx = tid; idx < 2048; idx += 256) {     // float4 granules
        int row = idx >> 4, q = idx & 15;
        int grow = row0 + row;
        if (grow < N_NODES)
            *(float4*)&g_xs[grow * 64 + q * 4] = *(float4*)&Gx[row * PLDG + q * 4];
    }

    // attention dots: thread pair (2r, 2r+1) covers row r (32 cols each)
    {
        int r = tid >> 1, hfc = tid & 1;
        const float* rowp = Gx + r * PLDG + hfc * 32;
        const float* sap = sa + hfc * 32;
        const float* sdp = sd + hfc * 32;
        float ps = 0.f, pd = 0.f;
        #pragma unroll
        for (int c = 0; c < 32; c++) {
            float v = rowp[c];
            ps += v * sap[c];
            pd += v * sdp[c];
        }
        ps += __shfl_xor_sync(0xffffffffu, ps, 1);
        pd += __shfl_xor_sync(0xffffffffu, pd, 1);
        int grow = row0 + r;
        if (hfc == 0 && grow < N_NODES) {
            g_asrc[grow] = ps;
            g_adst[grow] = pd;
        }
    }
}

// ---------------- CSR build --------------------------------------------------
__global__ void k_count(const int* __restrict__ eiw) {
    int e = blockIdx.x * blockDim.x + threadIdx.x;
    if (e < N_EDGES) {
        int dst = edge_at(eiw, N_EDGES + e);
        if ((unsigned)dst < (unsigned)N_NODES) atomicAdd(&g_cnt[dst], 1);
    }
}
__global__ void k_scan1() {
    __shared__ int sm[1024];
    int i = blockIdx.x * 1024 + threadIdx.x;
    int v = (i < N_NODES) ? g_cnt[i] : 0;
    sm[threadIdx.x] = v;
    __syncthreads();
    for (int off = 1; off < 1024; off <<= 1) {
        int t = 0;
        if ((int)threadIdx.x >= off) t = sm[threadIdx.x - off];
        __syncthreads();
        sm[threadIdx.x] += t;
        __syncthreads();
    }
    if (i < N_NODES) g_rowptr[i] = sm[threadIdx.x] - v;
    if (threadIdx.x == 1023) g_bsum[blockIdx.x] = sm[1023];
}
__global__ void k_scan2() {   // 128-thread smem scan over SCAN_BLOCKS sums
    __shared__ int sm[128];
    int t = threadIdx.x;
    int v = (t < SCAN_BLOCKS) ? g_bsum[t] : 0;
    sm[t] = v;
    __syncthreads();
    #pragma unroll
    for (int off = 1; off < 128; off <<= 1) {
        int u = (t >= off) ? sm[t - off] : 0;
        __syncthreads();
        sm[t] += u;
        __syncthreads();
    }
    if (t < SCAN_BLOCKS) g_boff[t] = sm[t] - v;   // exclusive
}
__global__ void k_scan3() {
    int i = blockIdx.x * 1024 + threadIdx.x;
    if (i < N_NODES) {
        int v = g_rowptr[i] + g_boff[blockIdx.x];
        g_rowptr[i] = v;
        g_cursor[i] = v;
    }
    if (i == 0) g_rowptr[N_NODES] = N_EDGES;
}
__global__ void k_fill(const int* __restrict__ eiw) {
    int e = blockIdx.x * blockDim.x + threadIdx.x;
    if (e < N_EDGES) {
        int dst = edge_at(eiw, N_EDGES + e);
        int src = edge_at(eiw, e);
        if ((unsigned)dst < (unsigned)N_NODES && (unsigned)src < (unsigned)N_NODES) {
            int pos = atomicAdd(&g_cursor[dst], 1);
            if ((unsigned)pos < (unsigned)N_EDGES) g_csr[pos] = src;
        }
    }
}

// ---------------- kernel 3: paired-half float4 softmax aggregation -----------
__global__ void k_agg(const float* __restrict__ bias) {
    const int warp = threadIdx.x >> 5;
    const int lane = threadIdx.x & 31;
    const int node = blockIdx.x * 8 + warp;

    const int start = g_rowptr[node];
    const int deg   = g_rowptr[node + 1] - start;
    const float adst = g_adst[node];

    const int hf = lane >> 4;        // which edge of the pair
    const int dl = lane & 15;        // dim group: dims 4*dl .. 4*dl+3

    unsigned long long accA = 0ull;  // dims (4dl, 4dl+1)
    unsigned long long accB = 0ull;  // dims (4dl+2, 4dl+3)
    float z = 0.f;

    for (int base = 0; base < deg; base += 32) {
        int k = base + lane;
        float p = 0.f;
        int s = 0;
        if (k < deg) {
            s = g_csr[start + k];
            float e = g_asrc[s] + adst;
            e = fmaxf(e, NEG * e);
            p = __expf(e);
        }
        z += p;
        int cnt = min(32, deg - base);
        int npair = (cnt + 1) >> 1;
        #pragma unroll 2
        for (int t = 0; t < npair; t++) {
            int srcl = 2 * t + hf;           // lane cnt (if hit) holds p=0 pad
            float pj = __shfl_sync(0xffffffffu, p, srcl);
            int   sj = __shfl_sync(0xffffffffu, s, srcl);
            ulonglong2 v = *(const ulonglong2*)&g_xs[sj * HID + 4 * dl];
            unsigned long long pp = pk2(pj, pj);
            accA = fma2(v.x, pp, accA);
            accB = fma2(v.y, pp, accB);
        }
    }
    // combine the two halves
    accA = add2(accA, __shfl_xor_sync(0xffffffffu, accA, 16));
    accB = add2(accB, __shfl_xor_sync(0xffffffffu, accB, 16));
    // z reduce over all 32 lanes
    #pragma unroll
    for (int o = 16; o; o >>= 1) z += __shfl_xor_sync(0xffffffffu, z, o);

    if (hf == 0) {
        float inv = 1.f / (z + 1e-16f);
        float2 a = up2(accA);
        float2 b = up2(accB);
        float4 bv = *(const float4*)&bias[4 * dl];
        float4 r;
        r.x = tanhf(a.x * inv + bv.x);
        r.y = tanhf(a.y * inv + bv.y);
        r.z = tanhf(b.x * inv + bv.z);
        r.w = tanhf(b.y * inv + bv.w);
        *(float4*)&g_xb[node * HID + 4 * dl] = r;
    }
}

// ---------------- kernel 4: WMMA fp16 LSTM step ------------------------------
__device__ __forceinline__ float sigf(float v) { return 1.f / (1.f + __expf(-v)); }

__global__ void __launch_bounds__(512, 1) k_lstm_wmma(
        const float* __restrict__ h_in, const float* __restrict__ c_in,
        float* __restrict__ out) {
    extern __shared__ unsigned char sm_raw[];
    __half* Asm = (__half*)sm_raw;                       // [128][LDA]
    float*  Gsm = (float*)(sm_raw + SM_A_BYTES);         // [128][LDG]

    const int tid = threadIdx.x;
    const int wid = tid >> 5;
    const int row0 = blockIdx.x * TILE_M;

    // stage A: fp32 -> fp16 (xb cols 0..63, h cols 64..127)
    for (int idx = tid; idx < 8192; idx += 512) {
        int row = idx >> 6;
        int k = (idx & 63) * 2;
        int grow = row0 + row;
        float2 f = make_float2(0.f, 0.f);
        if (grow < N_NODES) {
            f = (k < 64) ? *(const float2*)&g_xb[grow * 64 + k]
                         : *(const float2*)&h_in[grow * 64 + (k - 64)];
        }
        *(__half2*)&Asm[row * LDA + k] = __floats2half2_rn(f.x, f.y);
    }
    __syncthreads();

    // MMA: each warp 32 rows x 64 gates
    {
        const int wm = wid & 3;
        const int wn = wid >> 2;
        wmma::fragment<wmma::accumulator, 16, 16, 16, float> acc[2][4];
        #pragma unroll
        for (int i = 0; i < 2; i++)
            #pragma unroll
            for (int j = 0; j < 4; j++)
                wmma::fill_fragment(acc[i][j], 0.f);

        #pragma unroll
        for (int kk = 0; kk < 8; kk++) {
            wmma::fragment<wmma::matrix_a, 16, 16, 16, __half, wmma::row_major> a[2];
            #pragma unroll
            for (int i = 0; i < 2; i++)
                wmma::load_matrix_sync(a[i], Asm + (wm * 32 + i * 16) * LDA + kk * 16, LDA);
            #pragma unroll
            for (int j = 0; j < 4; j++) {
                wmma::fragment<wmma::matrix_b, 16, 16, 16, __half, wmma::col_major> b;
                wmma::load_matrix_sync(b, g_Bh16 + (wn * 64 + j * 16) * 128 + kk * 16, 128);
                wmma::mma_sync(acc[0][j], a[0], b, acc[0][j]);
                wmma::mma_sync(acc[1][j], a[1], b, acc[1][j]);
            }
        }
        #pragma unroll
        for (int i = 0; i < 2; i++)
            #pragma unroll
            for (int j = 0; j < 4; j++)
                wmma::store_matrix_sync(Gsm + (wm * 32 + i * 16) * LDG + wn * 64 + j * 16,
                                        acc[i][j], LDG, wmma::mem_row_major);
    }
    __syncthreads();

    // epilogue: torch gate order i,f,g,o
    const int row = tid >> 2;
    const int q = tid & 3;
    const int grow = row0 + row;
    if (grow < N_NODES) {
        const float* grow_g = Gsm + row * LDG;
        #pragma unroll
        for (int v4 = 0; v4 < 4; v4++) {
            int d = q * 16 + v4 * 4;
            float4 c0 = *(const float4*)&c_in[grow * 64 + d];
            float4 hv, cv;
            #pragma unroll
            for (int t = 0; t < 4; t++) {
                float ig = grow_g[d + t];
                float fg = grow_g[64 + d + t];
                float gv = grow_g[128 + d + t];
                float og = grow_g[192 + d + t];
                float c0v = (&c0.x)[t];
                float c1 = sigf(fg) * c0v + sigf(ig) * tanhf(gv);
                float h1 = sigf(og) * tanhf(c1);
                (&hv.x)[t] = h1;
                (&cv.x)[t] = c1;
            }
            *(float4*)&out[grow * 64 + d]          = hv;   // h1 flat
            *(float4*)&out[NH + grow * 64 + d]     = hv;   // h1[None]
            *(float4*)&out[2 * NH + grow * 64 + d] = cv;   // c1[None]
        }
    }
}

// ---------------- launch: fork-join; proj at profiled submission index 3 -----
extern "C" void kernel_launch(void* const* d_in, const int* in_sizes, int n_in,
                              void* d_out, int out_size) {
    const float* x   = (const float*)d_in[0];
    const int*   eiw = (const int*)d_in[1];     // edge_index, dtype-probed on device
    const float* h   = (const float*)d_in[2];
    const float* c   = (const float*)d_in[3];
    const float* Wg  = (const float*)d_in[4];
    const float* as  = (const float*)d_in[5];
    const float* ad  = (const float*)d_in[6];
    const float* bg  = (const float*)d_in[7];
    const float* Wih = (const float*)d_in[8];
    const float* Whh = (const float*)d_in[9];
    float* out = (float*)d_out;

    // lazily created handles (first call runs outside graph capture)
    static cudaStream_t s2 = nullptr;
    static cudaEvent_t evFork = nullptr, evJoin = nullptr;
    if (s2 == nullptr) {
        cudaStreamCreateWithFlags(&s2, cudaStreamNonBlocking);
        cudaEventCreateWithFlags(&evFork, cudaEventDisableTiming);
        cudaEventCreateWithFlags(&evJoin, cudaEventDisableTiming);
    }

    cudaFuncSetAttribute(k_lstm_wmma, cudaFuncAttributeMaxDynamicSharedMemorySize, SM_TOTAL);

    // idx 0: dtype probe + cnt zero, then fork
    k_detect<<<393, 256>>>(eiw);
    cudaEventRecord(evFork, 0);
    cudaStreamWaitEvent(s2, evFork, 0);

    // idx 1 (main): weight preps (needed by proj + lstm)
    k_prep<<<128, 256>>>(Wih, Whh, Wg);
    // idx 2 (s2): count
    k_count<<<(N_EDGES + 255) / 256, 256, 0, s2>>>(eiw);
    // idx 3 (main): projection  <-- profiled launch
    k_proj_wmma<<<N_TILES, 256>>>(x, as, ad);
    // rest of CSR chain (s2)
    k_scan1<<<SCAN_BLOCKS, 1024, 0, s2>>>();
    k_scan2<<<1, 128, 0, s2>>>();
    k_scan3<<<SCAN_BLOCKS, 1024, 0, s2>>>();
    k_fill<<<(N_EDGES + 255) / 256, 256, 0, s2>>>(eiw);
    cudaEventRecord(evJoin, s2);

    // join, then aggregation + LSTM
    cudaStreamWaitEvent(0, evJoin, 0);
    k_agg<<<N_NODES / 8, 256>>>(bg);
    k_lstm_wmma<<<N_TILES, 512, SM_TOTAL>>>(h, c, out);
}